// round 13
// baseline (speedup 1.0000x reference)
#include <cuda_runtime.h>
#include <cstdint>

typedef unsigned long long u64;

#define B_  16
#define N_  8192
#define C_  256
#define K_  4096

// Output layout (float32): [features][indices][adjacency][scores]
#define OFF_FEAT   ((size_t)0)
#define OFF_IDX    ((size_t)B_ * K_ * C_)
#define OFF_ADJ    (OFF_IDX + (size_t)B_ * K_)
#define OFF_SCORES (OFF_ADJ + (size_t)B_ * K_ * K_)

// Scratch (device globals; no allocation allowed)
__device__ __align__(16) unsigned short g_idx[B_ * K_];
__device__ int g_pos[B_ * N_];
__device__ __align__(16) u64 g_keys[B_ * N_];      // 1 MB sort scratch
__device__ unsigned int g_ctr;                     // work-steal counter

// Work-steal ranges
#define WORK_ADJ   8192                            // units [0, 8192): adj rows
#define FEAT_QUAD  2048                            // units [8192, 10240): feat
#define WORK_END   (WORK_ADJ + FEAT_QUAD)

// ---------------------------------------------------------------------------
// Bitonic convention (chunk-local): at stage (k, j), the lower element of a
// pair keeps the max iff (local_i & k)==0  => EVERY chunk independently
// sorted descending (required by the merge-path ranker).  Composite key
// flipped_score<<16 | (8191-idx) breaks ties by ascending index
// (jax.lax.top_k) and makes all keys unique => strict total order.
// ---------------------------------------------------------------------------
__device__ __forceinline__ void ce_pair(u64 &lo, u64 &hi, bool desc) {
    u64 a = lo, b = hi;
    u64 mx = a > b ? a : b;
    u64 mn = a > b ? b : a;
    lo = desc ? mx : mn;
    hi = desc ? mn : mx;
}
__device__ __forceinline__ u64 shfl_ce(u64 v, int j, bool keepmax) {
    u64 o = __shfl_xor_sync(0xFFFFFFFFu, v, j);
    u64 mx = v > o ? v : o;
    u64 mn = v > o ? o : v;
    return keepmax ? mx : mn;
}
__device__ __forceinline__ void smem_ce(u64* s, int i, int m, bool desc) {
    u64 a = s[i], c = s[m];
    if ((a < c) == desc) { s[i] = c; s[m] = a; }
}

// ---------------------------------------------------------------------------
// K1: sort each 1024-chunk fully DESCENDING (k=2..1024, chunk-local desc).
// grid B*8 = 128, block 256, 4 u64/thread, 8KB smem.  Builds keys, clears
// g_pos.  (Proven round-12 form.)
// ---------------------------------------------------------------------------
__global__ __launch_bounds__(256)
void sort1024_kernel(const float* __restrict__ scores)
{
    __shared__ u64 s[1024];
    const int b  = blockIdx.x >> 3;
    const int cb = (blockIdx.x & 7) << 10;          // batch-local chunk base
    const int t  = threadIdx.x;
    const int l  = t & 31;
    const int wbase = (t >> 5) << 7;                // warp*128 (chunk-local)
    const float* sc = scores + (size_t)b * N_;

    u64 v[4];
    #pragma unroll
    for (int e = 0; e < 4; e++) {
        int I = cb + wbase + e * 32 + l;            // batch-local (for key)
        unsigned u = __float_as_uint(sc[I]);
        u ^= (u & 0x80000000u) ? 0xFFFFFFFFu : 0x80000000u;
        v[e] = ((u64)u << 16) | (unsigned)(8191 - I);
        g_pos[b * N_ + cb + e * 256 + t] = -1;
    }

    // ---- register phase: k = 2..128 (chunk-local indices only) ----
    #pragma unroll
    for (int k = 2; k <= 128; k <<= 1) {
        #pragma unroll
        for (int eb = 2; eb >= 1; eb >>= 1) {
            const int j = eb << 5;
            if (j < k) {
                #pragma unroll
                for (int e = 0; e < 4; e++)
                    if (!(e & eb)) {
                        bool desc = (((wbase + e * 32) & k) == 0);
                        ce_pair(v[e], v[e | eb], desc);
                    }
            }
        }
        #pragma unroll
        for (int j = 16; j >= 1; j >>= 1) {
            if (j < k) {
                #pragma unroll
                for (int e = 0; e < 4; e++) {
                    bool desc = (((wbase + e * 32 + l) & k) == 0);
                    v[e] = shfl_ce(v[e], j, desc == ((l & j) == 0));
                }
            }
        }
    }

    // ---- k = 256, 512, 1024: smem stages j>=128, register tail j<=64 ----
    #pragma unroll 1
    for (int k = 256; k <= 1024; k <<= 1) {
        #pragma unroll
        for (int e = 0; e < 4; e++) s[wbase + e * 32 + l] = v[e];
        __syncthreads();
        #pragma unroll 1
        for (int j = k >> 1; j >= 128; j >>= 1) {
            #pragma unroll
            for (int q = 0; q < 2; q++) {
                int p = t + q * 256;                       // 0..511 pairs
                int i = ((p & ~(j - 1)) << 1) | (p & (j - 1));
                bool desc = ((i & k) == 0);                // chunk-local
                smem_ce(s, i, i + j, desc);
            }
            __syncthreads();
        }
        #pragma unroll
        for (int e = 0; e < 4; e++) v[e] = s[wbase + e * 32 + l];
        __syncthreads();
        #pragma unroll
        for (int eb = 2; eb >= 1; eb >>= 1) {
            #pragma unroll
            for (int e = 0; e < 4; e++)
                if (!(e & eb)) {
                    bool desc = (((wbase + e * 32) & k) == 0);
                    ce_pair(v[e], v[e | eb], desc);
                }
        }
        #pragma unroll
        for (int j = 16; j >= 1; j >>= 1) {
            #pragma unroll
            for (int e = 0; e < 4; e++) {
                bool desc = (((wbase + e * 32 + l) & k) == 0);
                v[e] = shfl_ce(v[e], j, desc == ((l & j) == 0));
            }
        }
    }

    #pragma unroll
    for (int e = 0; e < 4; e++)
        g_keys[(size_t)b * N_ + cb + wbase + e * 32 + l] = v[e];
}

// ---------------------------------------------------------------------------
// K2: merge-path rank + emit over 8 descending 1024-chunks (proven).
// Also resets the gather work-steal counter (stream-ordered before gather).
// ---------------------------------------------------------------------------
__global__ __launch_bounds__(512)
void rank_emit_kernel(float* __restrict__ out_idxf,
                      float* __restrict__ out_scores)
{
    const int gid = blockIdx.x * 512 + threadIdx.x;    // 0 .. B*N-1
    if (gid == 0) g_ctr = 0;                           // reset for gather

    const int b = gid >> 13;
    const int i = gid & (N_ - 1);
    const u64* keys = g_keys + (size_t)b * N_;
    const u64 x = keys[i];
    const int chunk = i >> 10;
    int rank = i & 1023;                               // greater elems in own chunk

    #pragma unroll
    for (int c = 0; c < 8; c++) {
        if (c == chunk) continue;
        const u64* a = keys + (c << 10);
        int lo = 0, hi = 1024;
        while (lo < hi) {                              // <= 11 iterations
            int mid = (lo + hi) >> 1;
            if (a[mid] > x) lo = mid + 1; else hi = mid;
        }
        rank += lo;                                    // # elements > x in chunk c
    }

    if (rank < K_) {
        int idx = 8191 - (int)(x & 0xFFFF);
        unsigned ku = (unsigned)(x >> 16);
        unsigned orig = (ku & 0x80000000u) ? (ku ^ 0x80000000u) : ~ku;
        g_idx[b * K_ + rank] = (unsigned short)idx;
        out_idxf[(size_t)b * K_ + rank]   = (float)idx;
        out_scores[(size_t)b * K_ + rank] = __uint_as_float(orig);
        g_pos[b * N_ + idx] = rank;
    }
}

// ---------------------------------------------------------------------------
// K3: persistent work-stealing gather.  592 CTAs pull units off g_ctr:
//   unit v in [0, 8192): adjacency source row v — stage 32KB row in SMEM,
//     serve every batch containing it (round-10 inner loop, unchanged);
//   unit v in [8192, 10240): feature quad — 4 coalesced 512-f4 tiles.
// Dynamic stealing removes wave quantization and the Binomial(16,1/2)
// per-row load imbalance; small feat units backfill the tail.
// ---------------------------------------------------------------------------
__global__ __launch_bounds__(512)
void gather_kernel(const float* __restrict__ A,
                   const float4* __restrict__ feat,
                   float* __restrict__ out_adj,
                   float4* __restrict__ out_feat)
{
    __shared__ float row[N_];   // 32 KB
    __shared__ unsigned s_v;

    for (;;) {
        __syncthreads();                       // protect row/s_v reuse
        if (threadIdx.x == 0) s_v = atomicAdd(&g_ctr, 1u);
        __syncthreads();
        const unsigned v = s_v;
        if (v >= WORK_END) return;

        if (v < WORK_ADJ) {
            const int r = v;
            const float4* src  = (const float4*)(A + (size_t)r * N_);
            float4*       rowv = (float4*)row;
            for (int t = threadIdx.x; t < N_ / 4; t += 512)
                rowv[t] = __ldcs(src + t);
            __syncthreads();

            #pragma unroll 1
            for (int b = 0; b < B_; ++b) {
                int i = g_pos[b * N_ + r];
                if (i < 0) continue;
                float4* obase = (float4*)(out_adj + ((size_t)b * K_ + i) * K_);
                const ushort4* idx4 = (const ushort4*)(g_idx + b * K_);
                for (int t = threadIdx.x; t < K_ / 4; t += 512) {
                    ushort4 c = idx4[t];
                    __stcs(obase + t,
                           make_float4(row[c.x], row[c.y], row[c.z], row[c.w]));
                }
            }
        } else {
            const int q = (int)(v - WORK_ADJ);          // 0..2047
            #pragma unroll
            for (int u = 0; u < 4; u++) {
                int o = (q * 4 + u) * 512 + threadIdx.x; // 0..4194303
                int frow = o >> 6;                       // C/4=64 f4/row
                int c    = o & 63;
                int b    = frow >> 12;                   // K rows/batch
                int rr   = g_idx[frow];
                __stcs(out_feat + o,
                       __ldcs(feat + ((size_t)(b << 13) + rr) * 64 + c));
            }
        }
    }
}

// ---------------------------------------------------------------------------
extern "C" void kernel_launch(void* const* d_in, const int* in_sizes, int n_in,
                              void* d_out, int out_size)
{
    const float* scores = (const float*)d_in[0];   // (B, N)
    const float* feat   = (const float*)d_in[1];   // (B, N, C)
    const float* adj    = (const float*)d_in[2];   // (N, N)
    float* out = (float*)d_out;

    float* out_feat   = out + OFF_FEAT;
    float* out_idxf   = out + OFF_IDX;
    float* out_adj    = out + OFF_ADJ;
    float* out_scores = out + OFF_SCORES;

    sort1024_kernel<<<B_ * 8, 256>>>(scores);
    rank_emit_kernel<<<B_ * N_ / 512, 512>>>(out_idxf, out_scores);

    gather_kernel<<<148 * 4, 512>>>(adj, (const float4*)feat,
                                    out_adj, (float4*)out_feat);
}

// round 14
// speedup vs baseline: 1.0235x; 1.0235x over previous
#include <cuda_runtime.h>
#include <cstdint>

typedef unsigned long long u64;

#define B_  16
#define N_  8192
#define C_  256
#define K_  4096

// Output layout (float32): [features][indices][adjacency][scores]
#define OFF_FEAT   ((size_t)0)
#define OFF_IDX    ((size_t)B_ * K_ * C_)
#define OFF_ADJ    (OFF_IDX + (size_t)B_ * K_)
#define OFF_SCORES (OFF_ADJ + (size_t)B_ * K_ * K_)

// Scratch (device globals; no allocation allowed)
__device__ __align__(16) unsigned short g_idx[B_ * K_];
__device__ int g_pos[B_ * N_];
__device__ __align__(16) u64 g_keys[B_ * N_];      // 1 MB sort scratch

// ---------------------------------------------------------------------------
// Bitonic convention (chunk-local): at stage (k, j), the lower element of a
// pair keeps the max iff (local_i & k)==0  => EVERY chunk independently
// sorted descending (required by the merge-path ranker).  Composite key
// flipped_score<<16 | (8191-idx) breaks ties by ascending index
// (jax.lax.top_k) and makes all keys unique => strict total order.
// ---------------------------------------------------------------------------
__device__ __forceinline__ void ce_pair(u64 &lo, u64 &hi, bool desc) {
    u64 a = lo, b = hi;
    u64 mx = a > b ? a : b;
    u64 mn = a > b ? b : a;
    lo = desc ? mx : mn;
    hi = desc ? mn : mx;
}
__device__ __forceinline__ u64 shfl_ce(u64 v, int j, bool keepmax) {
    u64 o = __shfl_xor_sync(0xFFFFFFFFu, v, j);
    u64 mx = v > o ? v : o;
    u64 mn = v > o ? o : v;
    return keepmax ? mx : mn;
}
__device__ __forceinline__ void smem_ce(u64* s, int i, int m, bool desc) {
    u64 a = s[i], c = s[m];
    if ((a < c) == desc) { s[i] = c; s[m] = a; }
}

// ---------------------------------------------------------------------------
// K1: sort each 1024-chunk fully DESCENDING (k=2..1024, chunk-local desc).
// grid B*8 = 128, block 256, 4 u64/thread, 8KB smem.  Builds keys, clears
// g_pos.  (Proven round-12 form, byte-identical.)
// ---------------------------------------------------------------------------
__global__ __launch_bounds__(256)
void sort1024_kernel(const float* __restrict__ scores)
{
    __shared__ u64 s[1024];
    const int b  = blockIdx.x >> 3;
    const int cb = (blockIdx.x & 7) << 10;          // batch-local chunk base
    const int t  = threadIdx.x;
    const int l  = t & 31;
    const int wbase = (t >> 5) << 7;                // warp*128 (chunk-local)
    const float* sc = scores + (size_t)b * N_;

    u64 v[4];
    #pragma unroll
    for (int e = 0; e < 4; e++) {
        int I = cb + wbase + e * 32 + l;            // batch-local (for key)
        unsigned u = __float_as_uint(sc[I]);
        u ^= (u & 0x80000000u) ? 0xFFFFFFFFu : 0x80000000u;
        v[e] = ((u64)u << 16) | (unsigned)(8191 - I);
        g_pos[b * N_ + cb + e * 256 + t] = -1;
    }

    // ---- register phase: k = 2..128 (chunk-local indices only) ----
    #pragma unroll
    for (int k = 2; k <= 128; k <<= 1) {
        #pragma unroll
        for (int eb = 2; eb >= 1; eb >>= 1) {
            const int j = eb << 5;
            if (j < k) {
                #pragma unroll
                for (int e = 0; e < 4; e++)
                    if (!(e & eb)) {
                        bool desc = (((wbase + e * 32) & k) == 0);
                        ce_pair(v[e], v[e | eb], desc);
                    }
            }
        }
        #pragma unroll
        for (int j = 16; j >= 1; j >>= 1) {
            if (j < k) {
                #pragma unroll
                for (int e = 0; e < 4; e++) {
                    bool desc = (((wbase + e * 32 + l) & k) == 0);
                    v[e] = shfl_ce(v[e], j, desc == ((l & j) == 0));
                }
            }
        }
    }

    // ---- k = 256, 512, 1024: smem stages j>=128, register tail j<=64 ----
    #pragma unroll 1
    for (int k = 256; k <= 1024; k <<= 1) {
        #pragma unroll
        for (int e = 0; e < 4; e++) s[wbase + e * 32 + l] = v[e];
        __syncthreads();
        #pragma unroll 1
        for (int j = k >> 1; j >= 128; j >>= 1) {
            #pragma unroll
            for (int q = 0; q < 2; q++) {
                int p = t + q * 256;                       // 0..511 pairs
                int i = ((p & ~(j - 1)) << 1) | (p & (j - 1));
                bool desc = ((i & k) == 0);                // chunk-local
                smem_ce(s, i, i + j, desc);
            }
            __syncthreads();
        }
        #pragma unroll
        for (int e = 0; e < 4; e++) v[e] = s[wbase + e * 32 + l];
        __syncthreads();
        #pragma unroll
        for (int eb = 2; eb >= 1; eb >>= 1) {
            #pragma unroll
            for (int e = 0; e < 4; e++)
                if (!(e & eb)) {
                    bool desc = (((wbase + e * 32) & k) == 0);
                    ce_pair(v[e], v[e | eb], desc);
                }
        }
        #pragma unroll
        for (int j = 16; j >= 1; j >>= 1) {
            #pragma unroll
            for (int e = 0; e < 4; e++) {
                bool desc = (((wbase + e * 32 + l) & k) == 0);
                v[e] = shfl_ce(v[e], j, desc == ((l & j) == 0));
            }
        }
    }

    #pragma unroll
    for (int e = 0; e < 4; e++)
        g_keys[(size_t)b * N_ + cb + wbase + e * 32 + l] = v[e];
}

// ---------------------------------------------------------------------------
// K2: merge-path rank + emit over 8 descending 1024-chunks, with the 7
// foreign-chunk binary searches INTERLEAVED (lo/hi arrays, 11 unrolled
// rounds, independent guarded loads each round => 7-way MLP instead of a
// 7x-serial dependent chain).  Invariant per chunk: a[0..lo) > x,
// a[hi..1024) <= x; rounds after convergence are predicated off (no OOB).
// ---------------------------------------------------------------------------
__global__ __launch_bounds__(512)
void rank_emit_kernel(float* __restrict__ out_idxf,
                      float* __restrict__ out_scores)
{
    const int gid = blockIdx.x * 512 + threadIdx.x;    // 0 .. B*N-1
    const int b = gid >> 13;
    const int i = gid & (N_ - 1);
    const u64* keys = g_keys + (size_t)b * N_;
    const u64 x = keys[i];
    const int chunk = i >> 10;

    int lo[8], hi[8];
    #pragma unroll
    for (int c = 0; c < 8; c++) {
        lo[c] = 0;
        hi[c] = (c == chunk) ? 0 : 1024;               // own chunk: no search
    }

    #pragma unroll
    for (int it = 0; it < 11; it++) {                  // ceil(log2(1025)) = 11
        #pragma unroll
        for (int c = 0; c < 8; c++) {
            if (lo[c] < hi[c]) {
                int mid = (lo[c] + hi[c]) >> 1;
                u64 val = keys[(c << 10) + mid];
                if (val > x) lo[c] = mid + 1; else hi[c] = mid;
            }
        }
    }

    int rank = i & 1023;                               // greater elems in own chunk
    #pragma unroll
    for (int c = 0; c < 8; c++) rank += lo[c];

    if (rank < K_) {
        int idx = 8191 - (int)(x & 0xFFFF);
        unsigned ku = (unsigned)(x >> 16);
        unsigned orig = (ku & 0x80000000u) ? (ku ^ 0x80000000u) : ~ku;
        g_idx[b * K_ + rank] = (unsigned short)idx;
        out_idxf[(size_t)b * K_ + rank]   = (float)idx;
        out_scores[(size_t)b * K_ + rank] = __uint_as_float(orig);
        g_pos[b * N_ + idx] = rank;
    }
}

// ---------------------------------------------------------------------------
// Combined gather — static grid 10240, INTERLEAVED unit mapping to keep the
// HBM read/write mix steady over time (adj units are 20R:80W, feat units
// 50R:50W; interleaving 4 adj : 1 feat keeps the bus mix uniform instead of
// flipping at the 85% mark).  Bodies are byte-identical to the proven
// round-10 forms; mapping is bijective:
//   v % 5 == 4  -> feat quad  q = v/5            (2048 quads x 4 tiles)
//   otherwise   -> adj row    r = (v/5)*4 + v%5  (8192 rows)
// ---------------------------------------------------------------------------
__global__ __launch_bounds__(512)
void gather_kernel(const float* __restrict__ A,
                   const float4* __restrict__ feat,
                   float* __restrict__ out_adj,
                   float4* __restrict__ out_feat)
{
    __shared__ float row[N_];   // 32 KB (adj branch only)
    const int v = blockIdx.x;
    const int g5 = v / 5;
    const int r5 = v - g5 * 5;

    if (r5 != 4) {
        const int r = g5 * 4 + r5;                      // 0..8191
        const float4* src  = (const float4*)(A + (size_t)r * N_);
        float4*       rowv = (float4*)row;
        for (int t = threadIdx.x; t < N_ / 4; t += 512)
            rowv[t] = __ldcs(src + t);
        __syncthreads();

        #pragma unroll 1
        for (int b = 0; b < B_; ++b) {
            int i = g_pos[b * N_ + r];
            if (i < 0) continue;
            float4* obase = (float4*)(out_adj + ((size_t)b * K_ + i) * K_);
            const ushort4* idx4 = (const ushort4*)(g_idx + b * K_);
            for (int t = threadIdx.x; t < K_ / 4; t += 512) {
                ushort4 c = idx4[t];
                __stcs(obase + t,
                       make_float4(row[c.x], row[c.y], row[c.z], row[c.w]));
            }
        }
    } else {
        const int q = g5;                               // 0..2047
        #pragma unroll
        for (int u = 0; u < 4; u++) {
            int o = (q * 4 + u) * 512 + threadIdx.x;    // 0..4194303
            int frow = o >> 6;                          // C/4=64 f4/row
            int c    = o & 63;
            int b    = frow >> 12;                      // K rows/batch
            int rr   = g_idx[frow];
            __stcs(out_feat + o,
                   __ldcs(feat + ((size_t)(b << 13) + rr) * 64 + c));
        }
    }
}

// ---------------------------------------------------------------------------
extern "C" void kernel_launch(void* const* d_in, const int* in_sizes, int n_in,
                              void* d_out, int out_size)
{
    const float* scores = (const float*)d_in[0];   // (B, N)
    const float* feat   = (const float*)d_in[1];   // (B, N, C)
    const float* adj    = (const float*)d_in[2];   // (N, N)
    float* out = (float*)d_out;

    float* out_feat   = out + OFF_FEAT;
    float* out_idxf   = out + OFF_IDX;
    float* out_adj    = out + OFF_ADJ;
    float* out_scores = out + OFF_SCORES;

    sort1024_kernel<<<B_ * 8, 256>>>(scores);
    rank_emit_kernel<<<B_ * N_ / 512, 512>>>(out_idxf, out_scores);

    gather_kernel<<<10240, 512>>>(adj, (const float4*)feat,
                                  out_adj, (float4*)out_feat);
}